// round 1
// baseline (speedup 1.0000x reference)
#include <cuda_runtime.h>

// BatteryRNNCell: B=4M elementwise battery state update + output voltage.
// Inputs (metadata order):
//  0: inputs [B,1] f32      1: states [B,8] f32   2: qMax [B] f32   3: Ro [B] f32
//  4: Wp0 [8,1]  5: bp0 [8]  6: Wp2 [4,8]  7: bp2 [4]
//  8: Wp4 [1,4]  9: bp4 [1] 10: Wn [1,1]  11: bn [1]
// Output: V [B] followed by XNew [B,8] (flattened, concatenated in return order).

#define DEVI __device__ __forceinline__

// Physical constants
#define R_CONST    8.3144621f
#define F_CONST    96487.0f
#define KN_C       20000.0f
#define KP_C       20000.0f
#define VOL_C      2.2e-05f
#define VOLS_C     (0.1f * VOL_C)
#define VOLB_C     (VOL_C - VOLS_C)
#define U0P_C      4.03f
#define U0N_C      0.01f

DEVI float fast_tanh(float x) {
    // tanh(x) = 1 - 2/(e^{2x}+1). Robust at both saturations, abs err ~1e-7.
    float e = __expf(2.0f * x);
    return 1.0f - __fdividef(2.0f, e + 1.0f);
}

DEVI float fast_asinh_pos(float u) {
    // u > 0 in this workload (i in [1,3], Jn0 > 0). asinh(u)=log(u+sqrt(u^2+1)).
    return __logf(u + sqrtf(fmaf(u, u, 1.0f)));
}

DEVI float clampf(float v, float lo, float hi) {
    return fminf(fmaxf(v, lo), hi);
}

__global__ void __launch_bounds__(256) battery_cell_kernel(
    const float* __restrict__ inputs,
    const float* __restrict__ states,
    const float* __restrict__ qMax,
    const float* __restrict__ Ro,
    const float* __restrict__ Wp0, const float* __restrict__ bp0,
    const float* __restrict__ Wp2, const float* __restrict__ bp2,
    const float* __restrict__ Wp4, const float* __restrict__ bp4,
    const float* __restrict__ Wn,  const float* __restrict__ bn,
    float* __restrict__ outV, float* __restrict__ outX, int n)
{
    int b = blockIdx.x * blockDim.x + threadIdx.x;
    if (b >= n) return;

    // ---- loads (coalesced) ----
    const float4* st4 = reinterpret_cast<const float4*>(states);
    float4 s0 = st4[2 * b];       // Tb, Vo, Vsn, Vsp
    float4 s1 = st4[2 * b + 1];   // qnB, qnS, qpB, qpS
    float i   = inputs[b];
    float qM  = qMax[b];
    float ro  = Ro[b];

    float Tb = s0.x, Vo = s0.y, Vsn = s0.z, Vsp = s0.w;
    float qnB = s1.x, qnS = s1.y, qpB = s1.z, qpS = s1.w;

    // qSMax = qMax * 10000 * VOLS/VOL = qMax * 1000
    float qSMax     = qM * 1000.0f;
    float inv_qSMax = __fdividef(1.0f, qSMax);

    // ---- getNextState ----
    float xpS = clampf(qpS * inv_qSMax, 1e-18f, 1.0f);
    float xnS = clampf(qnS * inv_qSMax, 1e-18f, 1.0f);
    // (1-x)^0.5 * x^0.5  (match reference's two sqrts for edge fidelity)
    float Jn0 = 1e-18f + KN_C * (sqrtf(1.0f - xnS) * sqrtf(xnS));
    float Jp0 = 1e-18f + KP_C * (sqrtf(1.0f - xpS) * sqrtf(xpS));

    // qdot = (qB/VOLB - qS/VOLS) / 7e6
    const float cB = 1.0f / (VOLB_C * 7.0e6f);
    const float cS = 1.0f / (VOLS_C * 7.0e6f);
    float qdn = qnB * cB - qnS * cS;
    float qdp = qpB * cB - qpS * cS;

    float Jn = i * 5000.0f;   // i / SN
    float Jp = i * 5000.0f;   // i / SP

    float VoNom  = i * ro * 10.0f;
    const float C1 = R_CONST / F_CONST / 0.5f;   // R*Tb/F/alpha factor
    float VsnNom = C1 * Tb * fast_asinh_pos(__fdividef(Jn, 2.0f * Jn0));
    float VspNom = C1 * Tb * fast_asinh_pos(__fdividef(Jp, 2.0f * Jp0));

    float Tb2  = Tb;
    float Vo2  = Vo  + (VoNom  - Vo ) * (1.0f / 10.0f);
    float Vsn2 = Vsn + (VsnNom - Vsn) * (1.0f / 90.0f);
    float Vsp2 = Vsp + (VspNom - Vsp) * (1.0f / 90.0f);
    float qnB2 = qnB - qdn;
    float qnS2 = qnS + qdn - i;
    float qpB2 = qpB - qdp;
    float qpS2 = qpS + i + qdp;

    // ---- getNextOutput ----
    float xpo = qpS2 * inv_qSMax;
    float xno = qnS2 * inv_qSMax;

    // MLP: 1 -> 8 (tanh) -> 4 (tanh) -> 1
    float h[8];
    #pragma unroll
    for (int j = 0; j < 8; j++)
        h[j] = fast_tanh(fmaf(__ldg(&Wp0[j]), xpo, __ldg(&bp0[j])));

    float VepMLP = __ldg(&bp4[0]);
    #pragma unroll
    for (int k = 0; k < 4; k++) {
        float a = __ldg(&bp2[k]);
        #pragma unroll
        for (int j = 0; j < 8; j++)
            a = fmaf(__ldg(&Wp2[k * 8 + j]), h[j], a);
        VepMLP = fmaf(__ldg(&Wp4[k]), fast_tanh(a), VepMLP);
    }
    float VenMLP = fmaf(xno, __ldg(&Wn[0]), __ldg(&bn[0]));

    float ratio_p = clampf(__fdividef(1.0f - xpo, xpo), 1e-18f, 1e18f);
    float ratio_n = clampf(__fdividef(1.0f - xno, xno), 1e-18f, 1e18f);
    const float C2 = R_CONST / F_CONST;
    float Vep = U0P_C + C2 * Tb2 * __logf(ratio_p) + VepMLP;
    float Ven = U0N_C + C2 * Tb2 * __logf(ratio_n) + VenMLP;

    float V = Vep - Ven - Vo2 - Vsn2 - Vsp2;

    // ---- stores ----
    outV[b] = V;
    float4* ox4 = reinterpret_cast<float4*>(outX);
    ox4[2 * b]     = make_float4(Tb2, Vo2, Vsn2, Vsp2);
    ox4[2 * b + 1] = make_float4(qnB2, qnS2, qpB2, qpS2);
}

extern "C" void kernel_launch(void* const* d_in, const int* in_sizes, int n_in,
                              void* d_out, int out_size) {
    const float* inputs = (const float*)d_in[0];
    const float* states = (const float*)d_in[1];
    const float* qMax   = (const float*)d_in[2];
    const float* Ro     = (const float*)d_in[3];
    const float* Wp0    = (const float*)d_in[4];
    const float* bp0    = (const float*)d_in[5];
    const float* Wp2    = (const float*)d_in[6];
    const float* bp2    = (const float*)d_in[7];
    const float* Wp4    = (const float*)d_in[8];
    const float* bp4    = (const float*)d_in[9];
    const float* Wn     = (const float*)d_in[10];
    const float* bn     = (const float*)d_in[11];

    int n = in_sizes[0];  // B (inputs is [B,1])
    float* outV = (float*)d_out;
    float* outX = outV + n;  // XNew [B,8] follows V [B]

    int threads = 256;
    int blocks = (n + threads - 1) / threads;
    battery_cell_kernel<<<blocks, threads>>>(
        inputs, states, qMax, Ro, Wp0, bp0, Wp2, bp2, Wp4, bp4, Wn, bn,
        outV, outX, n);
}